// round 2
// baseline (speedup 1.0000x reference)
#include <cuda_runtime.h>
#include <cuda_bf16.h>

// HungarianMatcher cost matrix, shapes hardcoded:
//   rows = bs*nq = 19200, T = 1280 targets, fp32 out [19200 x 1280].
//   cost = |pcx-tcx| + |pw-tw| + (cc + cr + 1) - inter/union - union/enclose
// (area==w in (cx,w) space; GIoU's +1 folded into the per-row constant).
//
// Structure: block = 8 rows x 1280 targets; 320 threads, 4 targets/thread,
// targets staged in shared SoA and hoisted to registers across the 8-row loop.
// T hardcoded -> STG offsets are immediates; row consts packed into one LDS.128.

#define QPER 8
#define NTHREADS 320
#define TT 1280            // targets (compile-time!)
#define NROWS 19200

__global__ __launch_bounds__(NTHREADS, 5)
void hm_cost_kernel(const float* __restrict__ logits,
                    const float* __restrict__ spans,
                    const float* __restrict__ tgt,
                    const float* __restrict__ ref,
                    float* __restrict__ out)
{
    __shared__ float s_tcx[TT], s_tw[TT], s_tx1[TT], s_tx2[TT];
    __shared__ float4 s_rowA[QPER];   // {cx, w, x1, x2}
    __shared__ float  s_rowC[QPER];   // cc + cr + 1

    const int tid  = threadIdx.x;
    const int row0 = blockIdx.x * QPER;

    // Stage targets into SoA shared (cx, w, x1, x2).
    const float2* tg2 = reinterpret_cast<const float2*>(tgt);
    #pragma unroll
    for (int k = 0; k < TT / NTHREADS; k++) {
        int j = tid + k * NTHREADS;
        float2 s = tg2[j];
        s_tcx[j] = s.x;
        s_tw[j]  = s.y;
        s_tx1[j] = fmaf(s.y, -0.5f, s.x);
        s_tx2[j] = fmaf(s.y,  0.5f, s.x);
    }

    // Per-row constants (one thread per row).
    if (tid < QPER) {
        int r = row0 + tid;
        float2 s  = reinterpret_cast<const float2*>(spans)[r];
        float cx = s.x, w = s.y;
        float x1 = fmaf(w, -0.5f, cx);
        float x2 = fmaf(w,  0.5f, cx);
        float2 lg = reinterpret_cast<const float2*>(logits)[r];
        float cc = -1.0f / (1.0f + __expf(lg.y - lg.x));   // -softmax[0] (2 classes)
        float2 rp = reinterpret_cast<const float2*>(ref)[r];
        float d0 = x1 - rp.x;
        float d1 = x2 - rp.y;
        float cr = sqrtf(d0 * d0 + d1 * d1);
        s_rowA[tid] = make_float4(cx, w, x1, x2);
        s_rowC[tid] = cc + cr + 1.0f;
    }
    __syncthreads();

    // Hoist this thread's 4 targets to registers (reused across 8 rows).
    const int tb = tid * 4;
    const float4 tc  = *reinterpret_cast<const float4*>(&s_tcx[tb]);
    const float4 tw  = *reinterpret_cast<const float4*>(&s_tw[tb]);
    const float4 t1  = *reinterpret_cast<const float4*>(&s_tx1[tb]);
    const float4 t2  = *reinterpret_cast<const float4*>(&s_tx2[tb]);

    // One base pointer; all row/target offsets are compile-time immediates.
    float* base = out + (size_t)row0 * TT + tb;

    #pragma unroll
    for (int q = 0; q < QPER; q++) {
        const float4 A = s_rowA[q];         // LDS.128 broadcast
        const float  c = s_rowC[q];         // LDS.32  broadcast
        const float cx = A.x, w = A.y, x1 = A.z, x2 = A.w;

        float4 o;
        {
            // --- element 0 ---
            float l1 = fabsf(cx - tc.x) + fabsf(w - tw.x);
            float it = fmaxf(fminf(x2, t2.x) - fmaxf(x1, t1.x), 0.0f);
            float un = (w + tw.x) - it;
            float en = fmaxf(x2, t2.x) - fminf(x1, t1.x);
            o.x = fmaf(-it, __frcp_rn(un), fmaf(-un, __frcp_rn(en), l1 + c));
        }
        {
            float l1 = fabsf(cx - tc.y) + fabsf(w - tw.y);
            float it = fmaxf(fminf(x2, t2.y) - fmaxf(x1, t1.y), 0.0f);
            float un = (w + tw.y) - it;
            float en = fmaxf(x2, t2.y) - fminf(x1, t1.y);
            o.y = fmaf(-it, __frcp_rn(un), fmaf(-un, __frcp_rn(en), l1 + c));
        }
        {
            float l1 = fabsf(cx - tc.z) + fabsf(w - tw.z);
            float it = fmaxf(fminf(x2, t2.z) - fmaxf(x1, t1.z), 0.0f);
            float un = (w + tw.z) - it;
            float en = fmaxf(x2, t2.z) - fminf(x1, t1.z);
            o.z = fmaf(-it, __frcp_rn(un), fmaf(-un, __frcp_rn(en), l1 + c));
        }
        {
            float l1 = fabsf(cx - tc.w) + fabsf(w - tw.w);
            float it = fmaxf(fminf(x2, t2.w) - fmaxf(x1, t1.w), 0.0f);
            float un = (w + tw.w) - it;
            float en = fmaxf(x2, t2.w) - fminf(x1, t1.w);
            o.w = fmaf(-it, __frcp_rn(un), fmaf(-un, __frcp_rn(en), l1 + c));
        }
        *reinterpret_cast<float4*>(base + q * TT) = o;   // STG.E.128 [R+imm]
    }
}

extern "C" void kernel_launch(void* const* d_in, const int* in_sizes, int n_in,
                              void* d_out, int out_size)
{
    const float* logits = (const float*)d_in[0];
    const float* spans  = (const float*)d_in[1];
    const float* tgt    = (const float*)d_in[2];
    const float* ref    = (const float*)d_in[3];
    float* out = (float*)d_out;

    hm_cost_kernel<<<NROWS / QPER, NTHREADS>>>(logits, spans, tgt, ref, out);
}

// round 3
// speedup vs baseline: 1.1301x; 1.1301x over previous
#include <cuda_runtime.h>
#include <cuda_bf16.h>

// HungarianMatcher cost matrix, 19200 rows x 1280 targets, fp32.
//
// Compressed math. With dc = cx - tc, hd = 0.5w - 0.5tw, halfS = 0.5w + 0.5tw,
// m = max(|dc|, |hd|)  [uses |a+b|+|a-b| = 2 max(|a|,|b|)]:
//   l1      = |dc| + 2|hd|
//   inter   = max(halfS - m, 0)
//   enclose = halfS + m
//   union   = 2*halfS - inter
//   cost    = l1 + C - inter/union - union/enclose,  C = cost_class + cost_ref + 1
// 14 instrs/element: 10 fma-pipe (5 in FFMA-imm rt=1 form), 2 FMNMX, 2 MUFU.RCP.

#define QPER 8
#define NTHREADS 320
#define TT 1280
#define NROWS 19200

__global__ __launch_bounds__(NTHREADS, 5)
void hm_cost_kernel(const float* __restrict__ logits,
                    const float* __restrict__ spans,
                    const float* __restrict__ tgt,
                    const float* __restrict__ ref,
                    float* __restrict__ out)
{
    __shared__ float  s_tc[TT], s_htw[TT];     // target cx, 0.5*tw
    __shared__ float4 s_row[QPER];             // {cx, 0.5*w, C, pad}

    const int tid  = threadIdx.x;
    const int row0 = blockIdx.x * QPER;

    // Stage targets: only (cx, 0.5*w) needed.
    const float2* tg2 = reinterpret_cast<const float2*>(tgt);
    #pragma unroll
    for (int k = 0; k < TT / NTHREADS; k++) {
        int j = tid + k * NTHREADS;
        float2 s = tg2[j];
        s_tc[j]  = s.x;
        s_htw[j] = 0.5f * s.y;
    }

    // Per-row constants.
    if (tid < QPER) {
        int r = row0 + tid;
        float2 s  = reinterpret_cast<const float2*>(spans)[r];
        float cx = s.x, hw = 0.5f * s.y;
        float2 lg = reinterpret_cast<const float2*>(logits)[r];
        float cc = -1.0f / (1.0f + __expf(lg.y - lg.x));   // -softmax prob of class 0
        float2 rp = reinterpret_cast<const float2*>(ref)[r];
        float d0 = (cx - hw) - rp.x;
        float d1 = (cx + hw) - rp.y;
        float cr = sqrtf(d0 * d0 + d1 * d1);
        s_row[tid] = make_float4(cx, hw, cc + cr + 1.0f, 0.0f);
    }
    __syncthreads();

    // Hoist 4 targets (2 floats each) to registers; reused across 8 rows.
    const int tb = tid * 4;
    const float4 tc  = *reinterpret_cast<const float4*>(&s_tc[tb]);
    const float4 htw = *reinterpret_cast<const float4*>(&s_htw[tb]);

    float* base = out + (size_t)row0 * TT + tb;

    #pragma unroll
    for (int q = 0; q < QPER; q++) {
        const float4 R = s_row[q];             // single LDS.128 broadcast
        const float cx = R.x, hw = R.y, C = R.z;

        float4 o;
        {
            float dc = fmaf(tc.x, -1.0f, cx);          // FFMA-imm
            float hd = fmaf(htw.x, -1.0f, hw);         // FFMA-imm
            float hs = hw + htw.x;
            float m  = fmaxf(fabsf(dc), fabsf(hd));    // FMNMX |..| (alu)
            float lc = fabsf(dc) + C;                  // FADD |..|
            float l1c = fmaf(fabsf(hd), 2.0f, lc);     // FFMA-imm
            float it = fmaxf(fmaf(m, -1.0f, hs), 0.0f);
            float en = hs + m;
            float un = fmaf(hs, 2.0f, -it);            // FFMA-imm
            float a  = fmaf(-it, __frcp_rn(un), l1c);
            o.x      = fmaf(-un, __frcp_rn(en), a);
        }
        {
            float dc = fmaf(tc.y, -1.0f, cx);
            float hd = fmaf(htw.y, -1.0f, hw);
            float hs = hw + htw.y;
            float m  = fmaxf(fabsf(dc), fabsf(hd));
            float lc = fabsf(dc) + C;
            float l1c = fmaf(fabsf(hd), 2.0f, lc);
            float it = fmaxf(fmaf(m, -1.0f, hs), 0.0f);
            float en = hs + m;
            float un = fmaf(hs, 2.0f, -it);
            float a  = fmaf(-it, __frcp_rn(un), l1c);
            o.y      = fmaf(-un, __frcp_rn(en), a);
        }
        {
            float dc = fmaf(tc.z, -1.0f, cx);
            float hd = fmaf(htw.z, -1.0f, hw);
            float hs = hw + htw.z;
            float m  = fmaxf(fabsf(dc), fabsf(hd));
            float lc = fabsf(dc) + C;
            float l1c = fmaf(fabsf(hd), 2.0f, lc);
            float it = fmaxf(fmaf(m, -1.0f, hs), 0.0f);
            float en = hs + m;
            float un = fmaf(hs, 2.0f, -it);
            float a  = fmaf(-it, __frcp_rn(un), l1c);
            o.z      = fmaf(-un, __frcp_rn(en), a);
        }
        {
            float dc = fmaf(tc.w, -1.0f, cx);
            float hd = fmaf(htw.w, -1.0f, hw);
            float hs = hw + htw.w;
            float m  = fmaxf(fabsf(dc), fabsf(hd));
            float lc = fabsf(dc) + C;
            float l1c = fmaf(fabsf(hd), 2.0f, lc);
            float it = fmaxf(fmaf(m, -1.0f, hs), 0.0f);
            float en = hs + m;
            float un = fmaf(hs, 2.0f, -it);
            float a  = fmaf(-it, __frcp_rn(un), l1c);
            o.w      = fmaf(-un, __frcp_rn(en), a);
        }
        *reinterpret_cast<float4*>(base + q * TT) = o;  // STG.E.128 [R+imm]
    }
}

extern "C" void kernel_launch(void* const* d_in, const int* in_sizes, int n_in,
                              void* d_out, int out_size)
{
    const float* logits = (const float*)d_in[0];
    const float* spans  = (const float*)d_in[1];
    const float* tgt    = (const float*)d_in[2];
    const float* ref    = (const float*)d_in[3];
    float* out = (float*)d_out;

    hm_cost_kernel<<<NROWS / QPER, NTHREADS>>>(logits, spans, tgt, ref, out);
}

// round 4
// speedup vs baseline: 1.2901x; 1.1415x over previous
#include <cuda_runtime.h>
#include <cuda_bf16.h>

// HungarianMatcher cost matrix, 19200 rows x 1280 targets, fp32.
//
// With dc = cx-tc, hd = 0.5w-0.5tw, hs = 0.5w+0.5tw, m = max(|dc|,|hd|):
//   l1 = |dc| + 2|hd|;  inter = max(hs-m,0);  enclose = hs+m;  union = 2hs-inter
//   cost = l1 + C - inter/union - union/enclose
// Fused division: inter/union + union/enclose = (it*en + un^2) * rcp(un*en).
// -> 15 instrs/el: 12 fma-pipe, 2 FMNMX, 1 MUFU.RCP.

#define QPER 8
#define NTHREADS 320
#define TT 1280
#define NROWS 19200

__device__ __forceinline__ float cost_el(float cx, float hw, float C,
                                         float tc, float htw)
{
    float dc  = cx - tc;
    float hd  = hw - htw;
    float hs  = hw + htw;
    float adc = fabsf(dc);
    float ahd = fabsf(hd);
    float m   = fmaxf(adc, ahd);             // FMNMX, |..| are modifiers
    float l1c = fmaf(ahd, 2.0f, adc + C);    // l1 + C
    float it  = fmaxf(hs - m, 0.0f);         // inter
    float en  = hs + m;                      // enclose
    float un  = fmaf(hs, 2.0f, -it);         // union
    float r   = __frcp_rn(un * en);          // single reciprocal
    float num = fmaf(un, un, it * en);       // it*en + un^2
    return fmaf(-num, r, l1c);
}

__global__ __launch_bounds__(NTHREADS)
void hm_cost_kernel(const float* __restrict__ logits,
                    const float* __restrict__ spans,
                    const float* __restrict__ tgt,
                    const float* __restrict__ ref,
                    float* __restrict__ out)
{
    __shared__ float  s_tc[TT], s_htw[TT];   // target cx, 0.5*tw
    __shared__ float4 s_row[QPER];           // {cx, 0.5*w, C, pad}

    const int tid  = threadIdx.x;
    const int row0 = blockIdx.x * QPER;

    // Stage targets: only (cx, 0.5*w) needed.
    const float2* tg2 = reinterpret_cast<const float2*>(tgt);
    #pragma unroll
    for (int k = 0; k < TT / NTHREADS; k++) {
        int j = tid + k * NTHREADS;
        float2 s = tg2[j];
        s_tc[j]  = s.x;
        s_htw[j] = 0.5f * s.y;
    }

    // Per-row constants.
    if (tid < QPER) {
        int r = row0 + tid;
        float2 s  = reinterpret_cast<const float2*>(spans)[r];
        float cx = s.x, hw = 0.5f * s.y;
        float2 lg = reinterpret_cast<const float2*>(logits)[r];
        float cc = -1.0f / (1.0f + __expf(lg.y - lg.x));   // -softmax prob class 0
        float2 rp = reinterpret_cast<const float2*>(ref)[r];
        float d0 = (cx - hw) - rp.x;
        float d1 = (cx + hw) - rp.y;
        float cr = sqrtf(d0 * d0 + d1 * d1);
        s_row[tid] = make_float4(cx, hw, cc + cr + 1.0f, 0.0f);
    }
    __syncthreads();

    // Hoist 4 targets (2 floats each) to registers; reused across 8 rows.
    const int tb = tid * 4;
    const float4 tc  = *reinterpret_cast<const float4*>(&s_tc[tb]);
    const float4 htw = *reinterpret_cast<const float4*>(&s_htw[tb]);

    float* base = out + (size_t)row0 * TT + tb;

    #pragma unroll
    for (int q = 0; q < QPER; q++) {
        const float4 R = s_row[q];           // one LDS.128 broadcast
        const float cx = R.x, hw = R.y, C = R.z;

        float4 o;
        o.x = cost_el(cx, hw, C, tc.x, htw.x);
        o.y = cost_el(cx, hw, C, tc.y, htw.y);
        o.z = cost_el(cx, hw, C, tc.z, htw.z);
        o.w = cost_el(cx, hw, C, tc.w, htw.w);
        *reinterpret_cast<float4*>(base + q * TT) = o;   // STG.E.128 [R+imm]
    }
}

extern "C" void kernel_launch(void* const* d_in, const int* in_sizes, int n_in,
                              void* d_out, int out_size)
{
    const float* logits = (const float*)d_in[0];
    const float* spans  = (const float*)d_in[1];
    const float* tgt    = (const float*)d_in[2];
    const float* ref    = (const float*)d_in[3];
    float* out = (float*)d_out;

    hm_cost_kernel<<<NROWS / QPER, NTHREADS>>>(logits, spans, tgt, ref, out);
}

// round 5
// speedup vs baseline: 1.3038x; 1.0106x over previous
#include <cuda_runtime.h>
#include <cuda_bf16.h>

// HungarianMatcher cost matrix, 19200 rows x 1280 targets, fp32.
//
// Per element (dc = cx-tc, hd = hw-htw, hs = hw+htw, m = max(|dc|,|hd|)):
//   cost = |dc| + 2|hd| + C - inter/union - union/enclose
//   inter = max(hs-m,0); enclose = hs+m; union = 2hs-inter
//   divisions fused: i/u + u/e = (i*e + u^2) * rcp(u*e)
// Elements processed in PAIRS with Blackwell packed f32x2 math (FFMA2/FADD2):
// 10 packed fma-pipe ops + 6 scalar fma + 4 FMNMX + 2 MUFU per pair.

#define QPER 8
#define NTHREADS 320
#define TT 1280
#define NROWS 19200

typedef unsigned long long u64;

__device__ __forceinline__ u64 pack2(float lo, float hi) {
    u64 r; asm("mov.b64 %0, {%1, %2};" : "=l"(r) : "f"(lo), "f"(hi)); return r;
}
__device__ __forceinline__ void unpack2(u64 v, float& lo, float& hi) {
    asm("mov.b64 {%0, %1}, %2;" : "=f"(lo), "=f"(hi) : "l"(v));
}
__device__ __forceinline__ u64 add2(u64 a, u64 b) {
    u64 r; asm("add.rn.f32x2 %0, %1, %2;" : "=l"(r) : "l"(a), "l"(b)); return r;
}
__device__ __forceinline__ u64 mul2(u64 a, u64 b) {
    u64 r; asm("mul.rn.f32x2 %0, %1, %2;" : "=l"(r) : "l"(a), "l"(b)); return r;
}
__device__ __forceinline__ u64 fma2(u64 a, u64 b, u64 c) {
    u64 r; asm("fma.rn.f32x2 %0, %1, %2, %3;" : "=l"(r) : "l"(a), "l"(b), "l"(c)); return r;
}

// packed {-1.0f, -1.0f}: turns fma2(x, NEG1, y) into y - x
#define NEG1_2 0xBF800000BF800000ULL

__device__ __forceinline__ void pair_cost(u64 cx2, u64 hw2, float C,
                                          u64 tc2, u64 htw2,
                                          float& oa, float& ob)
{
    u64 dc2  = fma2(tc2,  NEG1_2, cx2);    // cx - tc   (packed)
    u64 hd2  = fma2(htw2, NEG1_2, hw2);    // hw - htw
    u64 hs2  = add2(hw2, htw2);            // hw + htw
    float dca, dcb, hda, hdb;
    unpack2(dc2, dca, dcb);                // register aliasing (free)
    unpack2(hd2, hda, hdb);
    float ma = fmaxf(fabsf(dca), fabsf(hda));   // FMNMX (alu)
    float mb = fmaxf(fabsf(dcb), fabsf(hdb));
    u64 m2   = pack2(ma, mb);
    u64 d2   = fma2(m2, NEG1_2, hs2);      // hs - m
    float da, db;
    unpack2(d2, da, db);
    float ita = fmaxf(da, 0.0f);           // inter (FMNMX)
    float itb = fmaxf(db, 0.0f);
    u64 it2  = pack2(ita, itb);
    u64 en2  = add2(hs2, m2);              // enclose
    u64 hsx2 = add2(hs2, hs2);             // 2*hs
    u64 un2  = fma2(it2, NEG1_2, hsx2);    // union
    u64 ue2  = mul2(un2, en2);
    float uea, ueb;
    unpack2(ue2, uea, ueb);
    float ra = __frcp_rn(uea);             // MUFU.RCP
    float rb = __frcp_rn(ueb);
    u64 ite2 = mul2(it2, en2);
    u64 num2 = fma2(un2, un2, ite2);       // it*en + un^2
    float na, nb;
    unpack2(num2, na, nb);
    float l1a = fmaf(fabsf(hda), 2.0f, fabsf(dca) + C);   // FADD|..| + FFMA-imm
    float l1b = fmaf(fabsf(hdb), 2.0f, fabsf(dcb) + C);
    oa = fmaf(-na, ra, l1a);
    ob = fmaf(-nb, rb, l1b);
}

__global__ __launch_bounds__(NTHREADS)
void hm_cost_kernel(const float* __restrict__ logits,
                    const float* __restrict__ spans,
                    const float* __restrict__ tgt,
                    const float* __restrict__ ref,
                    float* __restrict__ out)
{
    __shared__ float  s_tc[TT], s_htw[TT];   // target cx, 0.5*tw (SoA)
    __shared__ float4 s_row[QPER];           // {cx, 0.5*w, C, pad}

    const int tid  = threadIdx.x;
    const int row0 = blockIdx.x * QPER;

    const float2* tg2 = reinterpret_cast<const float2*>(tgt);
    #pragma unroll
    for (int k = 0; k < TT / NTHREADS; k++) {
        int j = tid + k * NTHREADS;
        float2 s = tg2[j];
        s_tc[j]  = s.x;
        s_htw[j] = 0.5f * s.y;
    }

    if (tid < QPER) {
        int r = row0 + tid;
        float2 s  = reinterpret_cast<const float2*>(spans)[r];
        float cx = s.x, hw = 0.5f * s.y;
        float2 lg = reinterpret_cast<const float2*>(logits)[r];
        float cc = -1.0f / (1.0f + __expf(lg.y - lg.x));   // -softmax prob class 0
        float2 rp = reinterpret_cast<const float2*>(ref)[r];
        float d0 = (cx - hw) - rp.x;
        float d1 = (cx + hw) - rp.y;
        float cr = sqrtf(d0 * d0 + d1 * d1);
        s_row[tid] = make_float4(cx, hw, cc + cr + 1.0f, 0.0f);
    }
    __syncthreads();

    // 4 targets per thread = 2 packed pairs, loaded as one LDS.128 each array.
    const int tb = tid * 4;
    const ulonglong2 TC = *reinterpret_cast<const ulonglong2*>(&s_tc[tb]);
    const ulonglong2 HT = *reinterpret_cast<const ulonglong2*>(&s_htw[tb]);

    float* base = out + (size_t)row0 * TT + tb;

    #pragma unroll
    for (int q = 0; q < QPER; q++) {
        const float4 R = s_row[q];           // LDS.128 broadcast
        const float cx = R.x, hw = R.y, C = R.z;
        const u64 cx2 = pack2(cx, cx);
        const u64 hw2 = pack2(hw, hw);

        float4 o;
        pair_cost(cx2, hw2, C, TC.x, HT.x, o.x, o.y);
        pair_cost(cx2, hw2, C, TC.y, HT.y, o.z, o.w);
        *reinterpret_cast<float4*>(base + q * TT) = o;   // STG.E.128 [R+imm]
    }
}

extern "C" void kernel_launch(void* const* d_in, const int* in_sizes, int n_in,
                              void* d_out, int out_size)
{
    const float* logits = (const float*)d_in[0];
    const float* spans  = (const float*)d_in[1];
    const float* tgt    = (const float*)d_in[2];
    const float* ref    = (const float*)d_in[3];
    float* out = (float*)d_out;

    hm_cost_kernel<<<NROWS / QPER, NTHREADS>>>(logits, spans, tgt, ref, out);
}

// round 8
// speedup vs baseline: 1.5405x; 1.1816x over previous
#include <cuda_runtime.h>
#include <cuda_bf16.h>

// HungarianMatcher cost matrix, 19200 rows x 1280 targets, fp32.
//
// Per element (dc = cx-tc, hd = hw-htw, hs = hw+htw, m = max(|dc|,|hd|)):
//   cost = |dc| + 2|hd| + C - inter/union - union/enclose
//   inter = max(hs-m,0); enclose = hs+m; union = 2hs-inter
//   divisions fused: i/u + u/e = (i*e + u^2) * rcp(u*e)
// Element pairs via packed f32x2 (FFMA2/FADD2); reciprocal is a single
// MUFU.RCP (rcp.approx.f32) — NO Newton refinement (tolerance is 1e-3).

#define QPER 8
#define NTHREADS 320
#define TT 1280
#define NROWS 19200

typedef unsigned long long u64;

__device__ __forceinline__ u64 pack2(float lo, float hi) {
    u64 r; asm("mov.b64 %0, {%1, %2};" : "=l"(r) : "f"(lo), "f"(hi)); return r;
}
__device__ __forceinline__ void unpack2(u64 v, float& lo, float& hi) {
    asm("mov.b64 {%0, %1}, %2;" : "=f"(lo), "=f"(hi) : "l"(v));
}
__device__ __forceinline__ u64 add2(u64 a, u64 b) {
    u64 r; asm("add.rn.f32x2 %0, %1, %2;" : "=l"(r) : "l"(a), "l"(b)); return r;
}
__device__ __forceinline__ u64 mul2(u64 a, u64 b) {
    u64 r; asm("mul.rn.f32x2 %0, %1, %2;" : "=l"(r) : "l"(a), "l"(b)); return r;
}
__device__ __forceinline__ u64 fma2(u64 a, u64 b, u64 c) {
    u64 r; asm("fma.rn.f32x2 %0, %1, %2, %3;" : "=l"(r) : "l"(a), "l"(b), "l"(c)); return r;
}
__device__ __forceinline__ float rcp_fast(float x) {
    float r; asm("rcp.approx.f32 %0, %1;" : "=f"(r) : "f"(x)); return r;
}

// packed {-1.0f, -1.0f}: fma2(x, NEG1, y) == y - x
#define NEG1_2 0xBF800000BF800000ULL

__device__ __forceinline__ void pair_cost(u64 cx2, u64 hw2, float C,
                                          u64 tc2, u64 htw2,
                                          float& oa, float& ob)
{
    u64 dc2  = fma2(tc2,  NEG1_2, cx2);    // cx - tc   (packed)
    u64 hd2  = fma2(htw2, NEG1_2, hw2);    // hw - htw
    u64 hs2  = add2(hw2, htw2);            // hw + htw
    float dca, dcb, hda, hdb;
    unpack2(dc2, dca, dcb);                // register aliasing (free)
    unpack2(hd2, hda, hdb);
    float ma = fmaxf(fabsf(dca), fabsf(hda));   // FMNMX with |..| modifiers
    float mb = fmaxf(fabsf(dcb), fabsf(hdb));
    u64 m2   = pack2(ma, mb);
    u64 d2   = fma2(m2, NEG1_2, hs2);      // hs - m
    float da, db;
    unpack2(d2, da, db);
    float ita = fmaxf(da, 0.0f);           // inter
    float itb = fmaxf(db, 0.0f);
    u64 it2  = pack2(ita, itb);
    u64 en2  = add2(hs2, m2);              // enclose
    u64 hsx2 = add2(hs2, hs2);             // 2*hs
    u64 un2  = fma2(it2, NEG1_2, hsx2);    // union
    u64 ue2  = mul2(un2, en2);
    float uea, ueb;
    unpack2(ue2, uea, ueb);
    float ra = rcp_fast(uea);              // single MUFU.RCP, no refinement
    float rb = rcp_fast(ueb);
    u64 ite2 = mul2(it2, en2);
    u64 num2 = fma2(un2, un2, ite2);       // it*en + un^2
    float na, nb;
    unpack2(num2, na, nb);
    float l1a = fmaf(fabsf(hda), 2.0f, fabsf(dca) + C);
    float l1b = fmaf(fabsf(hdb), 2.0f, fabsf(dcb) + C);
    oa = fmaf(-na, ra, l1a);
    ob = fmaf(-nb, rb, l1b);
}

__global__ __launch_bounds__(NTHREADS)
void hm_cost_kernel(const float* __restrict__ logits,
                    const float* __restrict__ spans,
                    const float* __restrict__ tgt,
                    const float* __restrict__ ref,
                    float* __restrict__ out)
{
    __shared__ float  s_tc[TT], s_htw[TT];   // target cx, 0.5*tw (SoA)
    __shared__ float4 s_row[QPER];           // {cx, 0.5*w, C, pad}

    const int tid  = threadIdx.x;
    const int row0 = blockIdx.x * QPER;

    const float2* tg2 = reinterpret_cast<const float2*>(tgt);
    #pragma unroll
    for (int k = 0; k < TT / NTHREADS; k++) {
        int j = tid + k * NTHREADS;
        float2 s = tg2[j];
        s_tc[j]  = s.x;
        s_htw[j] = 0.5f * s.y;
    }

    if (tid < QPER) {
        int r = row0 + tid;
        float2 s  = reinterpret_cast<const float2*>(spans)[r];
        float cx = s.x, hw = 0.5f * s.y;
        float2 lg = reinterpret_cast<const float2*>(logits)[r];
        float cc = -rcp_fast(1.0f + __expf(lg.y - lg.x));  // -softmax prob class 0
        float2 rp = reinterpret_cast<const float2*>(ref)[r];
        float d0 = (cx - hw) - rp.x;
        float d1 = (cx + hw) - rp.y;
        float cr = sqrtf(d0 * d0 + d1 * d1);
        s_row[tid] = make_float4(cx, hw, cc + cr + 1.0f, 0.0f);
    }
    __syncthreads();

    // 4 targets per thread = 2 packed pairs; LDS.128 loads.
    const int tb = tid * 4;
    const ulonglong2 TC = *reinterpret_cast<const ulonglong2*>(&s_tc[tb]);
    const ulonglong2 HT = *reinterpret_cast<const ulonglong2*>(&s_htw[tb]);

    float* base = out + (size_t)row0 * TT + tb;

    #pragma unroll
    for (int q = 0; q < QPER; q++) {
        const float4 R = s_row[q];           // LDS.128 broadcast
        const float cx = R.x, hw = R.y, C = R.z;
        const u64 cx2 = pack2(cx, cx);
        const u64 hw2 = pack2(hw, hw);

        float4 o;
        pair_cost(cx2, hw2, C, TC.x, HT.x, o.x, o.y);
        pair_cost(cx2, hw2, C, TC.y, HT.y, o.z, o.w);
        *reinterpret_cast<float4*>(base + q * TT) = o;   // STG.E.128 [R+imm]
    }
}

extern "C" void kernel_launch(void* const* d_in, const int* in_sizes, int n_in,
                              void* d_out, int out_size)
{
    const float* logits = (const float*)d_in[0];
    const float* spans  = (const float*)d_in[1];
    const float* tgt    = (const float*)d_in[2];
    const float* ref    = (const float*)d_in[3];
    float* out = (float*)d_out;

    hm_cost_kernel<<<NROWS / QPER, NTHREADS>>>(logits, spans, tgt, ref, out);
}

// round 9
// speedup vs baseline: 1.6637x; 1.0799x over previous
#include <cuda_runtime.h>
#include <cuda_bf16.h>

// HungarianMatcher cost matrix, 19200 rows x 1280 targets, fp32.
//
// 1D-GIoU collapse: in 1D, overlap => union == enclose; disjoint => inter = 0,
// union = 2hs. Both cases give  it/un + un/en = 1 + (hs-m)/(hs+m), so
//   cost = |dc| + 2|hd| + (cc + cr) - (hs-m)/(hs+m)
// with dc = cx-tc, hd = hw-htw, hs = hw+htw, m = max(|dc|,|hd|).
// Per element-pair: 5 packed f32x2 fma ops, 2 FMNMX, 2 MUFU.RCP, 6 scalar fma.

#define QPER 16
#define NTHREADS 320
#define TT 1280
#define NROWS 19200

typedef unsigned long long u64;

__device__ __forceinline__ u64 pack2(float lo, float hi) {
    u64 r; asm("mov.b64 %0, {%1, %2};" : "=l"(r) : "f"(lo), "f"(hi)); return r;
}
__device__ __forceinline__ void unpack2(u64 v, float& lo, float& hi) {
    asm("mov.b64 {%0, %1}, %2;" : "=f"(lo), "=f"(hi) : "l"(v));
}
__device__ __forceinline__ u64 add2(u64 a, u64 b) {
    u64 r; asm("add.rn.f32x2 %0, %1, %2;" : "=l"(r) : "l"(a), "l"(b)); return r;
}
__device__ __forceinline__ u64 fma2(u64 a, u64 b, u64 c) {
    u64 r; asm("fma.rn.f32x2 %0, %1, %2, %3;" : "=l"(r) : "l"(a), "l"(b), "l"(c)); return r;
}
__device__ __forceinline__ float rcp_fast(float x) {
    float r; asm("rcp.approx.f32 %0, %1;" : "=f"(r) : "f"(x)); return r;
}

// packed {-1.0f,-1.0f}: fma2(x, NEG1, y) == y - x
#define NEG1_2 0xBF800000BF800000ULL

__device__ __forceinline__ void pair_cost(u64 cx2, u64 hw2, float C,
                                          u64 tc2, u64 htw2,
                                          float& oa, float& ob)
{
    u64 dc2  = fma2(tc2,  NEG1_2, cx2);      // cx - tc   (packed)
    u64 hd2  = fma2(htw2, NEG1_2, hw2);      // hw - htw
    u64 hs2  = add2(hw2, htw2);              // hw + htw
    float dca, dcb, hda, hdb;
    unpack2(dc2, dca, dcb);                  // register aliasing (free)
    unpack2(hd2, hda, hdb);
    float ma = fmaxf(fabsf(dca), fabsf(hda));    // FMNMX, |..| modifiers
    float mb = fmaxf(fabsf(dcb), fabsf(hdb));
    u64 m2   = pack2(ma, mb);
    u64 num2 = fma2(m2, NEG1_2, hs2);        // hs - m
    u64 den2 = add2(hs2, m2);                // hs + m
    float na, nb, da, db;
    unpack2(num2, na, nb);
    unpack2(den2, da, db);
    float ra = rcp_fast(da);                 // MUFU.RCP, no refinement
    float rb = rcp_fast(db);
    float l1a = fmaf(fabsf(hda), 2.0f, fabsf(dca) + C);
    float l1b = fmaf(fabsf(hdb), 2.0f, fabsf(dcb) + C);
    oa = fmaf(-na, ra, l1a);
    ob = fmaf(-nb, rb, l1b);
}

__global__ __launch_bounds__(NTHREADS)
void hm_cost_kernel(const float* __restrict__ logits,
                    const float* __restrict__ spans,
                    const float* __restrict__ tgt,
                    const float* __restrict__ ref,
                    float* __restrict__ out)
{
    __shared__ float s_tc[TT], s_htw[TT];        // target cx, 0.5*tw (SoA)
    __shared__ ulonglong2 s_rowP[QPER];          // { {cx,cx}, {hw,hw} } pre-packed
    __shared__ float s_rowC[QPER];               // cc + cr   (the +-1's cancel)

    const int tid  = threadIdx.x;
    const int row0 = blockIdx.x * QPER;

    const float2* tg2 = reinterpret_cast<const float2*>(tgt);
    #pragma unroll
    for (int k = 0; k < TT / NTHREADS; k++) {
        int j = tid + k * NTHREADS;
        float2 s = tg2[j];
        s_tc[j]  = s.x;
        s_htw[j] = 0.5f * s.y;
    }

    if (tid < QPER) {
        int r = row0 + tid;
        float2 s  = reinterpret_cast<const float2*>(spans)[r];
        float cx = s.x, hw = 0.5f * s.y;
        float2 lg = reinterpret_cast<const float2*>(logits)[r];
        float cc = -rcp_fast(1.0f + __expf(lg.y - lg.x));   // -softmax prob class 0
        float2 rp = reinterpret_cast<const float2*>(ref)[r];
        float d0 = (cx - hw) - rp.x;
        float d1 = (cx + hw) - rp.y;
        float cr = sqrtf(d0 * d0 + d1 * d1);
        ulonglong2 P;
        P.x = pack2(cx, cx);
        P.y = pack2(hw, hw);
        s_rowP[tid] = P;
        s_rowC[tid] = cc + cr;
    }
    __syncthreads();

    // 4 targets per thread = 2 packed pairs; LDS.128 loads, live across 16 rows.
    const int tb = tid * 4;
    const ulonglong2 TC = *reinterpret_cast<const ulonglong2*>(&s_tc[tb]);
    const ulonglong2 HT = *reinterpret_cast<const ulonglong2*>(&s_htw[tb]);

    float* base = out + (size_t)row0 * TT + tb;

    #pragma unroll
    for (int q = 0; q < QPER; q++) {
        const ulonglong2 P = s_rowP[q];          // LDS.128 broadcast (pre-packed)
        const float C = s_rowC[q];               // LDS.32 broadcast

        float4 o;
        pair_cost(P.x, P.y, C, TC.x, HT.x, o.x, o.y);
        pair_cost(P.x, P.y, C, TC.y, HT.y, o.z, o.w);
        *reinterpret_cast<float4*>(base + q * TT) = o;   // STG.E.128 [R+imm]
    }
}

extern "C" void kernel_launch(void* const* d_in, const int* in_sizes, int n_in,
                              void* d_out, int out_size)
{
    const float* logits = (const float*)d_in[0];
    const float* spans  = (const float*)d_in[1];
    const float* tgt    = (const float*)d_in[2];
    const float* ref    = (const float*)d_in[3];
    float* out = (float*)d_out;

    hm_cost_kernel<<<NROWS / QPER, NTHREADS>>>(logits, spans, tgt, ref, out);
}

// round 10
// speedup vs baseline: 1.6814x; 1.0107x over previous
#include <cuda_runtime.h>
#include <cuda_bf16.h>

// HungarianMatcher cost matrix, 19200 rows x 1280 targets, fp32.
//
// 1D-GIoU collapse: overlap => union==enclose; disjoint => inter=0, union=2hs.
// Both cases: inter/union + union/enclose = 1 + (hs-m)/(hs+m), so
//   cost = |dc| + 2|hd| + (cc + cr) - (hs-m)/(hs+m)
// dc = cx-tc, hd = hw-htw, hs = hw+htw, m = max(|dc|,|hd|).
//
// ALL-SCALAR: 10 instrs/element (3 FADD, 1 FMNMX, 2 FADD, 1 MUFU.RCP,
// 1 FADD, 2 FFMA), abs folded into source modifiers. No f32x2 pack/unpack
// (R7 showed the mov.b64 shuffles doubled the stream).

#define QPER 16
#define NTHREADS 320
#define TT 1280
#define NROWS 19200

__device__ __forceinline__ float rcp_fast(float x) {
    float r; asm("rcp.approx.f32 %0, %1;" : "=f"(r) : "f"(x)); return r;
}

__device__ __forceinline__ float cost_el(float cx, float hw, float C,
                                         float tc, float htw)
{
    float dc  = cx - tc;                     // FADD
    float hd  = hw - htw;                    // FADD
    float hs  = hw + htw;                    // FADD
    float m   = fmaxf(fabsf(dc), fabsf(hd)); // FMNMX |src| mods
    float num = hs - m;                      // FADD
    float den = hs + m;                      // FADD
    float r   = rcp_fast(den);               // MUFU.RCP (no refinement)
    float t   = fabsf(dc) + C;               // FADD |src|
    float l1  = fmaf(fabsf(hd), 2.0f, t);    // FFMA-imm
    return fmaf(-num, r, l1);                // FFMA -src
}

__global__ __launch_bounds__(NTHREADS)
void hm_cost_kernel(const float* __restrict__ logits,
                    const float* __restrict__ spans,
                    const float* __restrict__ tgt,
                    const float* __restrict__ ref,
                    float* __restrict__ out)
{
    __shared__ float  s_tc[TT], s_htw[TT];   // target cx, 0.5*tw (SoA)
    __shared__ float4 s_row[QPER];           // {cx, 0.5*w, C, pad}

    const int tid  = threadIdx.x;
    const int row0 = blockIdx.x * QPER;

    const float2* tg2 = reinterpret_cast<const float2*>(tgt);
    #pragma unroll
    for (int k = 0; k < TT / NTHREADS; k++) {
        int j = tid + k * NTHREADS;
        float2 s = tg2[j];
        s_tc[j]  = s.x;
        s_htw[j] = 0.5f * s.y;
    }

    if (tid < QPER) {
        int r = row0 + tid;
        float2 s  = reinterpret_cast<const float2*>(spans)[r];
        float cx = s.x, hw = 0.5f * s.y;
        float2 lg = reinterpret_cast<const float2*>(logits)[r];
        float cc = -rcp_fast(1.0f + __expf(lg.y - lg.x));   // -softmax prob class 0
        float2 rp = reinterpret_cast<const float2*>(ref)[r];
        float d0 = (cx - hw) - rp.x;
        float d1 = (cx + hw) - rp.y;
        float cr = sqrtf(d0 * d0 + d1 * d1);
        s_row[tid] = make_float4(cx, hw, cc + cr, 0.0f);    // +-1's cancel
    }
    __syncthreads();

    // 4 targets per thread (scalar regs), live across all 16 rows.
    const int tb = tid * 4;
    const float4 tc = *reinterpret_cast<const float4*>(&s_tc[tb]);
    const float4 ht = *reinterpret_cast<const float4*>(&s_htw[tb]);

    float* base = out + (size_t)row0 * TT + tb;

    #pragma unroll
    for (int q = 0; q < QPER; q++) {
        const float4 R = s_row[q];           // one LDS.128 broadcast per row
        const float cx = R.x, hw = R.y, C = R.z;

        float4 o;
        o.x = cost_el(cx, hw, C, tc.x, ht.x);
        o.y = cost_el(cx, hw, C, tc.y, ht.y);
        o.z = cost_el(cx, hw, C, tc.z, ht.z);
        o.w = cost_el(cx, hw, C, tc.w, ht.w);
        *reinterpret_cast<float4*>(base + q * TT) = o;   // STG.E.128 [R+imm]
    }
}

extern "C" void kernel_launch(void* const* d_in, const int* in_sizes, int n_in,
                              void* d_out, int out_size)
{
    const float* logits = (const float*)d_in[0];
    const float* spans  = (const float*)d_in[1];
    const float* tgt    = (const float*)d_in[2];
    const float* ref    = (const float*)d_in[3];
    float* out = (float*)d_out;

    hm_cost_kernel<<<NROWS / QPER, NTHREADS>>>(logits, spans, tgt, ref, out);
}

// round 12
// speedup vs baseline: 1.7207x; 1.0234x over previous
#include <cuda_runtime.h>
#include <cuda_bf16.h>

// HungarianMatcher cost matrix, 19200 rows x 1280 targets, fp32.
//
// 1D-GIoU collapse + ratio rewrite:
//   -(hs-m)/(hs+m) = -1 + m / (0.5*hs + 0.5*m)
//   cost = |dc| + 2|hd| + (cc + cr - 1) + m/den,  den = 0.5*htw + hqq + 0.5*m
// dc = cx-tc, hd = hw-htw (hw=0.5w, htw=0.5tw), hqq = 0.25w, m = max(|dc|,|hd|).
// 9 instrs/element: 3 FADD, 1 FMNMX, 3 FFMA(-imm), 1 MUFU.RCP, 1 FFMA.
// QPER=32 -> grid=600 ~= one resident wave; prologue amortized over 32 rows.

#define QPER 32
#define NTHREADS 320
#define TT 1280
#define NROWS 19200

__device__ __forceinline__ float rcp_fast(float x) {
    float r; asm("rcp.approx.f32 %0, %1;" : "=f"(r) : "f"(x)); return r;
}

__device__ __forceinline__ float cost_el(float cx, float hw, float hqq, float C,
                                         float tc, float htw)
{
    float dc   = cx - tc;                      // FADD
    float hd   = hw - htw;                     // FADD
    float hs_h = fmaf(htw, 0.5f, hqq);         // FFMA-imm: 0.25(w+tw)
    float m    = fmaxf(fabsf(dc), fabsf(hd));  // FMNMX |src|
    float den  = fmaf(m, 0.5f, hs_h);          // FFMA-imm: 0.5(hs+m)
    float r    = rcp_fast(den);                // MUFU.RCP
    float t    = fabsf(dc) + C;                // FADD |src|
    float l1   = fmaf(fabsf(hd), 2.0f, t);     // FFMA-imm
    return fmaf(m, r, l1);                     // FFMA
}

__global__ __launch_bounds__(NTHREADS)
void hm_cost_kernel(const float* __restrict__ logits,
                    const float* __restrict__ spans,
                    const float* __restrict__ tgt,
                    const float* __restrict__ ref,
                    float* __restrict__ out)
{
    __shared__ float  s_tc[TT], s_htw[TT];   // target cx, 0.5*tw (SoA)
    __shared__ float4 s_row[QPER];           // {cx, 0.5w, 0.25w, cc+cr-1}

    const int tid  = threadIdx.x;
    const int row0 = blockIdx.x * QPER;

    const float2* tg2 = reinterpret_cast<const float2*>(tgt);
    #pragma unroll
    for (int k = 0; k < TT / NTHREADS; k++) {
        int j = tid + k * NTHREADS;
        float2 s = tg2[j];
        s_tc[j]  = s.x;
        s_htw[j] = 0.5f * s.y;
    }

    if (tid < QPER) {
        int r = row0 + tid;
        float2 s  = reinterpret_cast<const float2*>(spans)[r];
        float cx = s.x, hw = 0.5f * s.y;
        float2 lg = reinterpret_cast<const float2*>(logits)[r];
        float cc = -rcp_fast(1.0f + __expf(lg.y - lg.x));   // -softmax prob class 0
        float2 rp = reinterpret_cast<const float2*>(ref)[r];
        float d0 = (cx - hw) - rp.x;
        float d1 = (cx + hw) - rp.y;
        float cr = sqrtf(d0 * d0 + d1 * d1);
        s_row[tid] = make_float4(cx, hw, 0.5f * hw, cc + cr - 1.0f);
    }
    __syncthreads();

    // 4 targets per thread (8 scalar regs), live across all 32 rows.
    const int tb = tid * 4;
    const float4 tc = *reinterpret_cast<const float4*>(&s_tc[tb]);
    const float4 ht = *reinterpret_cast<const float4*>(&s_htw[tb]);

    float* base = out + (size_t)row0 * TT + tb;

    #pragma unroll
    for (int q = 0; q < QPER; q++) {
        const float4 R = s_row[q];           // one LDS.128 broadcast per row
        const float cx = R.x, hw = R.y, hqq = R.z, C = R.w;

        float4 o;
        o.x = cost_el(cx, hw, hqq, C, tc.x, ht.x);
        o.y = cost_el(cx, hw, hqq, C, tc.y, ht.y);
        o.z = cost_el(cx, hw, hqq, C, tc.z, ht.z);
        o.w = cost_el(cx, hw, hqq, C, tc.w, ht.w);
        *reinterpret_cast<float4*>(base + q * TT) = o;   // STG.E.128 [R+imm]
    }
}

extern "C" void kernel_launch(void* const* d_in, const int* in_sizes, int n_in,
                              void* d_out, int out_size)
{
    const float* logits = (const float*)d_in[0];
    const float* spans  = (const float*)d_in[1];
    const float* tgt    = (const float*)d_in[2];
    const float* ref    = (const float*)d_in[3];
    float* out = (float*)d_out;

    hm_cost_kernel<<<NROWS / QPER, NTHREADS>>>(logits, spans, tgt, ref, out);
}